// round 8
// baseline (speedup 1.0000x reference)
#include <cuda_runtime.h>

// Problem constants
#define Bsz 512
#define Tn  2048
#define Dn  64
#define Hn  66
#define Gn  264          // 4*H
#define RPB 4            // batch rows per block
#define NBLK (Bsz / RPB) // 128 blocks, 1 per SM

// Register-weight tiling
#define NG   88          // gate-row groups (3 rows each: 88*3 = 264)
#define SPL  4           // K splits
#define RG   3           // gate rows per thread
#define KC   34          // K-chunk floats (K padded 130 -> 136)
#define KP   136         // padded K
#define VP   136         // v row pitch (floats); 136*4B, 8B-aligned pairs
#define NTHR (NG * SPL)  // 352 threads = 11 warps

typedef unsigned long long ull;

// Inter-kernel scratch
__device__ float g_hT[Bsz * Hn];
__device__ float g_wp[Hn];
__device__ float g_pc[Hn];

// ---- packed f32x2 helpers (Blackwell) ----
__device__ __forceinline__ ull fma2(ull a, ull b, ull c) {
    ull d;
    asm("fma.rn.f32x2 %0, %1, %2, %3;" : "=l"(d) : "l"(a), "l"(b), "l"(c));
    return d;
}
__device__ __forceinline__ float hadd2(ull a) {
    float x, y;
    asm("mov.b64 {%0, %1}, %2;" : "=f"(x), "=f"(y) : "l"(a));
    return x + y;
}
__device__ __forceinline__ ull pack2(float a, float b) {
    ull r;
    asm("mov.b64 %0, {%1, %2};" : "=l"(r) : "f"(a), "f"(b));
    return r;
}

__device__ __forceinline__ float sigf(float x) {
    return 1.0f / (1.0f + __expf(-x));
}
__device__ __forceinline__ float tanh_fast(float x) {
    float e = __expf(-2.0f * fabsf(x));
    float r = (1.0f - e) / (1.0f + e);
    return copysignf(r, x);
}

// Concatenated-weight fetch: Wcat[g][k] = W_ih[g][k] (k<64) | W_hh[g][k-64] (k<130) | 0
__device__ __forceinline__ float wcat_ld(const float* __restrict__ Wih,
                                         const float* __restrict__ Whh,
                                         int g, int k) {
    if (k < Dn)        return Wih[g * Dn + k];
    if (k < Dn + Hn)   return Whh[g * Hn + (k - Dn)];
    return 0.0f;
}

__global__ void __launch_bounds__(NTHR, 1) lstm_kernel(
    const float* __restrict__ x,      // [B, T, D]
    const float* __restrict__ W_ih,   // [4H, D]
    const float* __restrict__ W_hh,   // [4H, H]
    const float* __restrict__ b_ih,   // [4H]
    const float* __restrict__ b_hh)   // [4H]
{
    __shared__ float v_s[RPB * VP];            // per-row concat(x_t, h_{t-1}, pad)
    __shared__ float part_s[SPL * RPB * Gn];   // K-split partial gates
    __shared__ float bias_s[Gn];

    const int tid  = threadIdx.x;
    const int row0 = blockIdx.x * RPB;

    const int s  = tid / NG;          // K-split 0..3 (warp-major: lanes share s mostly)
    const int ng = tid - s * NG;      // 0..87
    const int g0 = ng * RG;           // first of 3 gate rows
    const int kb = s * KC;            // K-chunk base (floats)

    // ---- one-time init ----
    for (int i = tid; i < RPB * VP; i += NTHR) v_s[i] = 0.0f;
    for (int i = tid; i < Gn; i += NTHR) bias_s[i] = b_ih[i] + b_hh[i];

    // weight tile -> registers (fully unrolled, static indices; ~102 regs)
    ull w[RG][KC / 2];
    #pragma unroll
    for (int gi = 0; gi < RG; ++gi) {
        #pragma unroll
        for (int kk = 0; kk < KC / 2; ++kk) {
            int g = g0 + gi;
            int k = kb + 2 * kk;
            w[gi][kk] = pack2(wcat_ld(W_ih, W_hh, g, k),
                              wcat_ld(W_ih, W_hh, g, k + 1));
        }
    }

    // x-loader mapping (256 threads) and update mapping (264 threads)
    const int r_l = tid >> 6;         // 0..3
    const int d_l = tid & 63;         // 0..63
    if (tid < RPB * Dn) {
        v_s[r_l * VP + d_l] = x[(row0 + r_l) * (Tn * Dn) + d_l];
    }
    const int ur = tid / Hn;          // 0..3  (valid for tid < 264)
    const int uj = tid - ur * Hn;     // 0..65
    float c_st = 0.0f, h_last = 0.0f;
    __syncthreads();

    for (int t = 0; t < Tn; ++t) {
        // prefetch x for t+1 (DRAM latency hidden under the gate loop)
        float xv = 0.0f;
        if (tid < RPB * Dn && t + 1 < Tn) {
            xv = x[(row0 + r_l) * (Tn * Dn) + (t + 1) * Dn + d_l];
        }

        // ---- gate partials: 12 fma2 per K-pair, 4 broadcast LDS.64 ----
        ull a0[RG], a1[RG], a2[RG], a3[RG];
        #pragma unroll
        for (int gi = 0; gi < RG; ++gi) { a0[gi] = 0; a1[gi] = 0; a2[gi] = 0; a3[gi] = 0; }

        #pragma unroll
        for (int kk = 0; kk < KC / 2; ++kk) {
            ull v0 = *(const ull*)(v_s + 0 * VP + kb + 2 * kk);
            ull v1 = *(const ull*)(v_s + 1 * VP + kb + 2 * kk);
            ull v2 = *(const ull*)(v_s + 2 * VP + kb + 2 * kk);
            ull v3 = *(const ull*)(v_s + 3 * VP + kb + 2 * kk);
            #pragma unroll
            for (int gi = 0; gi < RG; ++gi) {
                a0[gi] = fma2(w[gi][kk], v0, a0[gi]);
                a1[gi] = fma2(w[gi][kk], v1, a1[gi]);
                a2[gi] = fma2(w[gi][kk], v2, a2[gi]);
                a3[gi] = fma2(w[gi][kk], v3, a3[gi]);
            }
        }

        // store partials: addr stride 3 across lanes -> conflict-free
        #pragma unroll
        for (int gi = 0; gi < RG; ++gi) {
            part_s[(s * RPB + 0) * Gn + g0 + gi] = hadd2(a0[gi]);
            part_s[(s * RPB + 1) * Gn + g0 + gi] = hadd2(a1[gi]);
            part_s[(s * RPB + 2) * Gn + g0 + gi] = hadd2(a2[gi]);
            part_s[(s * RPB + 3) * Gn + g0 + gi] = hadd2(a3[gi]);
        }
        __syncthreads();

        // stash prefetched x_{t+1} (x region, no overlap with h region)
        if (tid < RPB * Dn) v_s[r_l * VP + d_l] = xv;

        // ---- pointwise cell update (c lives in this thread's register) ----
        if (tid < Gn) {
            float gs[4];
            #pragma unroll
            for (int q = 0; q < 4; ++q) {
                int gr = q * Hn + uj;
                float v = bias_s[gr];
                #pragma unroll
                for (int ss = 0; ss < SPL; ++ss)
                    v += part_s[(ss * RPB + ur) * Gn + gr];
                gs[q] = v;
            }
            float gi_ = sigf(gs[0]);
            float gf  = sigf(gs[1]);
            float gg  = tanh_fast(gs[2]);
            float go  = sigf(gs[3]);
            c_st   = gf * c_st + gi_ * gg;
            h_last = go * tanh_fast(c_st);
            v_s[ur * VP + Dn + uj] = h_last;   // h region [64:130)
        }
        __syncthreads();
    }

    if (tid < Gn) g_hT[(row0 + ur) * Hn + uj] = h_last;
}

// ---- BN stats + folded FC weights: one block per feature ----
__global__ void bn_stats_kernel(
    const float* __restrict__ gamma,
    const float* __restrict__ beta,
    const float* __restrict__ fcw)
{
    __shared__ float sm[64], sm2[64];
    const int f   = blockIdx.x;   // 0..65
    const int tid = threadIdx.x;  // 64 threads

    float s = 0.0f, sq = 0.0f;
    for (int b = tid; b < Bsz; b += 64) {
        float v = g_hT[b * Hn + f];
        s += v; sq += v * v;
    }
    sm[tid] = s; sm2[tid] = sq;
    __syncthreads();
    for (int o = 32; o > 0; o >>= 1) {
        if (tid < o) { sm[tid] += sm[tid + o]; sm2[tid] += sm2[tid + o]; }
        __syncthreads();
    }
    if (tid == 0) {
        float mean = sm[0] * (1.0f / Bsz);
        float var  = sm2[0] * (1.0f / Bsz) - mean * mean;  // biased (jnp.var)
        float rs   = rsqrtf(var + 1e-5f);
        float wv   = gamma[f] * rs * fcw[f];
        g_wp[f] = wv;
        g_pc[f] = beta[f] * fcw[f] - mean * wv;
    }
}

// logits[b] = fc_b + sum_j pc[j] + sum_j hT[b][j]*wp[j]   (all L2-resident)
__global__ void fc_kernel(const float* __restrict__ fcb, float* __restrict__ out)
{
    const int b = blockIdx.x * blockDim.x + threadIdx.x;
    if (b >= Bsz) return;
    float acc = fcb[0];
    #pragma unroll
    for (int j = 0; j < Hn; ++j) acc += g_pc[j];
    #pragma unroll
    for (int j = 0; j < Hn; ++j) acc += g_hT[b * Hn + j] * g_wp[j];
    out[b] = acc;
}

extern "C" void kernel_launch(void* const* d_in, const int* in_sizes, int n_in,
                              void* d_out, int out_size)
{
    const float* x     = (const float*)d_in[0];
    const float* W_ih  = (const float*)d_in[1];
    const float* W_hh  = (const float*)d_in[2];
    const float* b_ih  = (const float*)d_in[3];
    const float* b_hh  = (const float*)d_in[4];
    const float* gamma = (const float*)d_in[5];
    const float* beta  = (const float*)d_in[6];
    const float* fcw   = (const float*)d_in[7];
    const float* fcb   = (const float*)d_in[8];

    lstm_kernel<<<NBLK, NTHR>>>(x, W_ih, W_hh, b_ih, b_hh);
    bn_stats_kernel<<<Hn, 64>>>(gamma, beta, fcw);
    fc_kernel<<<2, 256>>>(fcb, (float*)d_out);
}

// round 12
// speedup vs baseline: 1.0953x; 1.0953x over previous
#include <cuda_runtime.h>

// Problem constants
#define Bsz 512
#define Tn  2048
#define Dn  64
#define Hn  66
#define Gn  264          // 4*H
#define RPB 4            // batch rows per block
#define NBLK (Bsz / RPB) // 128 blocks, 1 per SM

// Thread = (feature j, K-split s). 4 splits in the low lane bits -> quad shuffles.
#define SPL 4
#define NF  72                 // padded feature count (66 real + 6 pad)
#define NTHR (NF * SPL)        // 288 threads = 9 full warps
#define KC  34                 // K-chunk per split (K = 130 padded to 136)
#define VP  136                // v row pitch (floats)

typedef unsigned long long ull;

// Inter-kernel scratch
__device__ float g_hT[Bsz * Hn];
__device__ float g_wp[Hn];
__device__ float g_pc[Hn];

// ---- packed f32x2 helpers (Blackwell) ----
__device__ __forceinline__ ull fma2(ull a, ull b, ull c) {
    ull d;
    asm("fma.rn.f32x2 %0, %1, %2, %3;" : "=l"(d) : "l"(a), "l"(b), "l"(c));
    return d;
}
__device__ __forceinline__ float hadd2(ull a) {
    float x, y;
    asm("mov.b64 {%0, %1}, %2;" : "=f"(x), "=f"(y) : "l"(a));
    return x + y;
}
__device__ __forceinline__ ull pack2(float a, float b) {
    ull r;
    asm("mov.b64 %0, {%1, %2};" : "=l"(r) : "f"(a), "f"(b));
    return r;
}

__device__ __forceinline__ float sigf(float x) {
    return 1.0f / (1.0f + __expf(-x));
}
__device__ __forceinline__ float tanh_fast(float x) {
    float e = __expf(-2.0f * fabsf(x));
    float r = (1.0f - e) / (1.0f + e);
    return copysignf(r, x);
}

// Concatenated-weight fetch: Wcat[g][k] = W_ih[g][k] (k<64) | W_hh[g][k-64] (k<130) | 0
__device__ __forceinline__ float wcat_ld(const float* __restrict__ Wih,
                                         const float* __restrict__ Whh,
                                         int g, int k, bool valid) {
    if (!valid)          return 0.0f;
    if (k < Dn)          return Wih[g * Dn + k];
    if (k < Dn + Hn)     return Whh[g * Hn + (k - Dn)];
    return 0.0f;
}

__global__ void __launch_bounds__(NTHR, 1) lstm_kernel(
    const float* __restrict__ x,      // [B, T, D]
    const float* __restrict__ W_ih,   // [4H, D]
    const float* __restrict__ W_hh,   // [4H, H]
    const float* __restrict__ b_ih,   // [4H]
    const float* __restrict__ b_hh)   // [4H]
{
    __shared__ float v_s[2 * RPB * VP];   // double-buffered concat(x_t, h_{t-1}, pad)

    const int tid  = threadIdx.x;
    const int row0 = blockIdx.x * RPB;

    const int j  = tid >> 2;         // feature 0..71 (66..71 = pad lanes)
    const int s  = tid & 3;          // K-split 0..3 == batch row for the pointwise
    const int kb = s * KC;           // K-chunk base
    const bool valid = (j < Hn);

    // ---- zero both v buffers (pad region must stay 0 forever) ----
    for (int i = tid; i < 2 * RPB * VP; i += NTHR) v_s[i] = 0.0f;

    // ---- weights for 4 gates of feature j, K-chunk kb..kb+33 -> 68 ull regs ----
    ull w[4][KC / 2];
    #pragma unroll
    for (int g = 0; g < 4; ++g) {
        const int grow = g * Hn + (valid ? j : 0);
        #pragma unroll
        for (int kk = 0; kk < KC / 2; ++kk) {
            const int k = kb + 2 * kk;
            w[g][kk] = pack2(wcat_ld(W_ih, W_hh, grow, k,     valid),
                             wcat_ld(W_ih, W_hh, grow, k + 1, valid));
        }
    }
    // per-gate bias (added after the cross-split reduction)
    float bz[4];
    #pragma unroll
    for (int g = 0; g < 4; ++g) {
        const int grow = g * Hn + (valid ? j : 0);
        bz[g] = valid ? (b_ih[grow] + b_hh[grow]) : 0.0f;
    }

    // x loader mapping (first 256 threads)
    const int r_l = tid >> 6;        // 0..3
    const int d_l = tid & 63;        // 0..63
    if (tid < RPB * Dn) {
        v_s[r_l * VP + d_l] = x[(row0 + r_l) * (Tn * Dn) + d_l];
    }
    __syncthreads();

    float c_st = 0.0f, h_last = 0.0f;
    int buf = 0;

    for (int t = 0; t < Tn; ++t) {
        // prefetch x_{t+1} (DRAM latency hidden under the gate loop)
        float xv = 0.0f;
        if (tid < RPB * Dn && t + 1 < Tn) {
            xv = x[(row0 + r_l) * (Tn * Dn) + (t + 1) * Dn + d_l];
        }

        const float* vb = v_s + buf * (RPB * VP);

        // ---- gate partials: per iter 4 broadcast LDS.64 + 16 fma2 ----
        ull acc[4][RPB];
        #pragma unroll
        for (int g = 0; g < 4; ++g)
            #pragma unroll
            for (int r = 0; r < RPB; ++r) acc[g][r] = 0ull;

        #pragma unroll
        for (int kk = 0; kk < KC / 2; ++kk) {
            ull v0 = *(const ull*)(vb + 0 * VP + kb + 2 * kk);
            ull v1 = *(const ull*)(vb + 1 * VP + kb + 2 * kk);
            ull v2 = *(const ull*)(vb + 2 * VP + kb + 2 * kk);
            ull v3 = *(const ull*)(vb + 3 * VP + kb + 2 * kk);
            #pragma unroll
            for (int g = 0; g < 4; ++g) {
                acc[g][0] = fma2(w[g][kk], v0, acc[g][0]);
                acc[g][1] = fma2(w[g][kk], v1, acc[g][1]);
                acc[g][2] = fma2(w[g][kk], v2, acc[g][2]);
                acc[g][3] = fma2(w[g][kk], v3, acc[g][3]);
            }
        }

        // ---- cross-split reduction: quad butterfly (no SMEM, no extra barrier) ----
        float gr[4][RPB];
        #pragma unroll
        for (int g = 0; g < 4; ++g)
            #pragma unroll
            for (int r = 0; r < RPB; ++r) gr[g][r] = hadd2(acc[g][r]);
        #pragma unroll
        for (int g = 0; g < 4; ++g)
            #pragma unroll
            for (int r = 0; r < RPB; ++r)
                gr[g][r] += __shfl_xor_sync(0xffffffffu, gr[g][r], 1);
        #pragma unroll
        for (int g = 0; g < 4; ++g)
            #pragma unroll
            for (int r = 0; r < RPB; ++r)
                gr[g][r] += __shfl_xor_sync(0xffffffffu, gr[g][r], 2);

        // lane s handles batch row s: pick its 4 gate sums (SEL chain, no dyn index)
        float G[4];
        #pragma unroll
        for (int g = 0; g < 4; ++g) {
            float v = gr[g][0];
            if (s == 1) v = gr[g][1];
            if (s == 2) v = gr[g][2];
            if (s == 3) v = gr[g][3];
            G[g] = v + bz[g];
        }

        // ---- pointwise LSTM cell update (c in this thread's register) ----
        float gi = sigf(G[0]);
        float gf = sigf(G[1]);
        float gg = tanh_fast(G[2]);
        float go = sigf(G[3]);
        c_st   = gf * c_st + gi * gg;
        h_last = go * tanh_fast(c_st);

        // ---- write next buffer: x_{t+1} and h_t (both into buf^1) ----
        float* vn = v_s + (buf ^ 1) * (RPB * VP);
        if (tid < RPB * Dn) vn[r_l * VP + d_l] = xv;
        if (valid)          vn[s * VP + Dn + j] = h_last;  // conflict-free (j+8s banks)

        buf ^= 1;
        __syncthreads();   // the ONE barrier per step
    }

    if (valid) g_hT[(row0 + s) * Hn + j] = h_last;
}

// ---- BN stats + folded FC weights: one block per feature ----
__global__ void bn_stats_kernel(
    const float* __restrict__ gamma,
    const float* __restrict__ beta,
    const float* __restrict__ fcw)
{
    __shared__ float sm[64], sm2[64];
    const int f   = blockIdx.x;   // 0..65
    const int tid = threadIdx.x;  // 64 threads

    float s = 0.0f, sq = 0.0f;
    for (int b = tid; b < Bsz; b += 64) {
        float v = g_hT[b * Hn + f];
        s += v; sq += v * v;
    }
    sm[tid] = s; sm2[tid] = sq;
    __syncthreads();
    for (int o = 32; o > 0; o >>= 1) {
        if (tid < o) { sm[tid] += sm[tid + o]; sm2[tid] += sm2[tid + o]; }
        __syncthreads();
    }
    if (tid == 0) {
        float mean = sm[0] * (1.0f / Bsz);
        float var  = sm2[0] * (1.0f / Bsz) - mean * mean;  // biased (jnp.var)
        float rs   = rsqrtf(var + 1e-5f);
        float wv   = gamma[f] * rs * fcw[f];
        g_wp[f] = wv;
        g_pc[f] = beta[f] * fcw[f] - mean * wv;
    }
}

// logits[b] = fc_b + sum_j pc[j] + sum_j hT[b][j]*wp[j]   (all L2-resident)
__global__ void fc_kernel(const float* __restrict__ fcb, float* __restrict__ out)
{
    const int b = blockIdx.x * blockDim.x + threadIdx.x;
    if (b >= Bsz) return;
    float acc = fcb[0];
    #pragma unroll
    for (int j = 0; j < Hn; ++j) acc += g_pc[j];
    #pragma unroll
    for (int j = 0; j < Hn; ++j) acc += g_hT[b * Hn + j] * g_wp[j];
    out[b] = acc;
}

extern "C" void kernel_launch(void* const* d_in, const int* in_sizes, int n_in,
                              void* d_out, int out_size)
{
    const float* x     = (const float*)d_in[0];
    const float* W_ih  = (const float*)d_in[1];
    const float* W_hh  = (const float*)d_in[2];
    const float* b_ih  = (const float*)d_in[3];
    const float* b_hh  = (const float*)d_in[4];
    const float* gamma = (const float*)d_in[5];
    const float* beta  = (const float*)d_in[6];
    const float* fcw   = (const float*)d_in[7];
    const float* fcb   = (const float*)d_in[8];

    lstm_kernel<<<NBLK, NTHR>>>(x, W_ih, W_hh, b_ih, b_hh);
    bn_stats_kernel<<<Hn, 64>>>(gamma, beta, fcw);
    fc_kernel<<<2, 256>>>(fcb, (float*)d_out);
}

// round 15
// speedup vs baseline: 1.0997x; 1.0041x over previous
#include <cuda_runtime.h>

// Problem constants
#define Bsz 512
#define Tn  2048
#define Dn  64
#define Hn  66
#define Gn  264          // 4*H
#define RPB 4            // batch rows per block
#define NBLK (Bsz / RPB) // 128 blocks, 1 per SM

// Thread = (feature j, gate-half g2, K-split s):  tid = (j*2 + g2)*4 + s
#define SPL 4
#define NF  68                 // padded feature count (66 real + 2 pad)
#define NTHR (NF * 2 * SPL)    // 544 threads = 17 warps
#define KC  36                 // K-chunk per split (K = 130 padded to 144) -> 144B, 16B-aligned
#define VP  144                // v row pitch (floats); rows 576B, 16B-aligned

typedef unsigned long long ull;

// Inter-kernel scratch
__device__ float g_hT[Bsz * Hn];
__device__ float g_wp[Hn];
__device__ float g_pc[Hn];

// ---- packed f32x2 helpers (Blackwell) ----
__device__ __forceinline__ ull fma2(ull a, ull b, ull c) {
    ull d;
    asm("fma.rn.f32x2 %0, %1, %2, %3;" : "=l"(d) : "l"(a), "l"(b), "l"(c));
    return d;
}
__device__ __forceinline__ float hadd2(ull a) {
    float x, y;
    asm("mov.b64 {%0, %1}, %2;" : "=f"(x), "=f"(y) : "l"(a));
    return x + y;
}
__device__ __forceinline__ ull pack2(float a, float b) {
    ull r;
    asm("mov.b64 %0, {%1, %2};" : "=l"(r) : "f"(a), "f"(b));
    return r;
}

__device__ __forceinline__ float sigf(float x) {
    return 1.0f / (1.0f + __expf(-x));
}
__device__ __forceinline__ float tanh_fast(float x) {
    float e = __expf(-2.0f * fabsf(x));
    float r = (1.0f - e) / (1.0f + e);
    return copysignf(r, x);
}

// Concatenated-weight fetch: Wcat[g][k] = W_ih[g][k] (k<64) | W_hh[g][k-64] (k<130) | 0
__device__ __forceinline__ float wcat_ld(const float* __restrict__ Wih,
                                         const float* __restrict__ Whh,
                                         int g, int k, bool valid) {
    if (!valid)          return 0.0f;
    if (k < Dn)          return Wih[g * Dn + k];
    if (k < Dn + Hn)     return Whh[g * Hn + (k - Dn)];
    return 0.0f;          // pad region [130,144)
}

__global__ void __launch_bounds__(NTHR, 1) lstm_kernel(
    const float* __restrict__ x,      // [B, T, D]
    const float* __restrict__ W_ih,   // [4H, D]
    const float* __restrict__ W_hh,   // [4H, H]
    const float* __restrict__ b_ih,   // [4H]
    const float* __restrict__ b_hh)   // [4H]
{
    __shared__ __align__(16) float v_s[2 * RPB * VP];  // double-buffered concat(x_t, h_{t-1}, pad)

    const int tid  = threadIdx.x;
    const int row0 = blockIdx.x * RPB;

    const int j   = tid >> 3;        // feature 0..67 (66,67 = pad)
    const int g2  = (tid >> 2) & 1;  // gate half: 0 -> {i,f}, 1 -> {g,o}
    const int s   = tid & 3;         // K-split == batch row for the pointwise
    const int kb  = s * KC;          // K-chunk base (s*144B -> 16B-aligned)
    const bool valid = (j < Hn);

    // ---- zero both v buffers (pad region must stay 0 forever) ----
    for (int i = tid; i < 2 * RPB * VP; i += NTHR) v_s[i] = 0.0f;

    // ---- weights: 2 gates of feature j, K-chunk kb..kb+35 -> 36 ull regs ----
    ull w[2][KC / 2];
    float bz[2];
    #pragma unroll
    for (int g = 0; g < 2; ++g) {
        const int q    = 2 * g2 + g;               // global gate 0..3
        const int grow = q * Hn + (valid ? j : 0); // weight row
        #pragma unroll
        for (int kk = 0; kk < KC / 2; ++kk) {
            const int k = kb + 2 * kk;
            w[g][kk] = pack2(wcat_ld(W_ih, W_hh, grow, k,     valid),
                             wcat_ld(W_ih, W_hh, grow, k + 1, valid));
        }
        bz[g] = valid ? (b_ih[grow] + b_hh[grow]) : 0.0f;
    }

    // x loader mapping (first 256 threads)
    const int r_l = tid >> 6;        // 0..3 (for tid < 256)
    const int d_l = tid & 63;        // 0..63
    if (tid < RPB * Dn) {
        v_s[r_l * VP + d_l] = x[(row0 + r_l) * (Tn * Dn) + d_l];
    }
    __syncthreads();

    const bool p1 = (s & 1);
    const bool p2 = ((s >> 1) & 1);
    float c_st = 0.0f, h_last = 0.0f;
    int buf = 0;

    for (int t = 0; t < Tn; ++t) {
        // prefetch x_{t+1} (DRAM latency hidden under the gate loop)
        float xv = 0.0f;
        if (tid < RPB * Dn && t + 1 < Tn) {
            xv = x[(row0 + r_l) * (Tn * Dn) + (t + 1) * Dn + d_l];
        }

        const float* vb = v_s + buf * (RPB * VP);

        // ---- gate partials: 9 x {4 LDS.128 + 16 fma2} (all 16B-aligned) ----
        ull acc[2][RPB];
        #pragma unroll
        for (int g = 0; g < 2; ++g)
            #pragma unroll
            for (int r = 0; r < RPB; ++r) acc[g][r] = 0ull;

        #pragma unroll
        for (int q4 = 0; q4 < KC / 4; ++q4) {     // 4 floats (= 2 pairs) per load
            ulonglong2 V0 = *(const ulonglong2*)(vb + 0 * VP + kb + 4 * q4);
            ulonglong2 V1 = *(const ulonglong2*)(vb + 1 * VP + kb + 4 * q4);
            ulonglong2 V2 = *(const ulonglong2*)(vb + 2 * VP + kb + 4 * q4);
            ulonglong2 V3 = *(const ulonglong2*)(vb + 3 * VP + kb + 4 * q4);
            #pragma unroll
            for (int g = 0; g < 2; ++g) {
                acc[g][0] = fma2(w[g][2 * q4],     V0.x, acc[g][0]);
                acc[g][0] = fma2(w[g][2 * q4 + 1], V0.y, acc[g][0]);
                acc[g][1] = fma2(w[g][2 * q4],     V1.x, acc[g][1]);
                acc[g][1] = fma2(w[g][2 * q4 + 1], V1.y, acc[g][1]);
                acc[g][2] = fma2(w[g][2 * q4],     V2.x, acc[g][2]);
                acc[g][2] = fma2(w[g][2 * q4 + 1], V2.y, acc[g][2]);
                acc[g][3] = fma2(w[g][2 * q4],     V3.x, acc[g][3]);
                acc[g][3] = fma2(w[g][2 * q4 + 1], V3.y, acc[g][3]);
            }
        }

        // horizontal add; inject bias once (split 0 only)
        float f0[RPB], f1[RPB];
        #pragma unroll
        for (int r = 0; r < RPB; ++r) { f0[r] = hadd2(acc[0][r]); f1[r] = hadd2(acc[1][r]); }
        if (s == 0) {
            #pragma unroll
            for (int r = 0; r < RPB; ++r) { f0[r] += bz[0]; f1[r] += bz[1]; }
        }

        // ---- value-halving butterfly over s (SEL + shfl) ----
        // Stage 1 (xor 1): keep rows with bit0(r)==p1, receive partner's kept rows.
        float s0a = p1 ? f0[0] : f0[1];   // send: rows I discard
        float s0b = p1 ? f0[2] : f0[3];
        float s1a = p1 ? f1[0] : f1[1];
        float s1b = p1 ? f1[2] : f1[3];
        float A0 = (p1 ? f0[1] : f0[0]) + __shfl_xor_sync(0xffffffffu, s0a, 1); // row p1
        float B0 = (p1 ? f0[3] : f0[2]) + __shfl_xor_sync(0xffffffffu, s0b, 1); // row p1+2
        float A1 = (p1 ? f1[1] : f1[0]) + __shfl_xor_sync(0xffffffffu, s1a, 1);
        float B1 = (p1 ? f1[3] : f1[2]) + __shfl_xor_sync(0xffffffffu, s1b, 1);

        // Stage 2 (xor 2): keep row with bit1(r)==p2  ->  row == s, full 4-split sum.
        float t0 = p2 ? A0 : B0;          // send the discarded one
        float t1 = p2 ? A1 : B1;
        float G0 = (p2 ? B0 : A0) + __shfl_xor_sync(0xffffffffu, t0, 2); // gate 2*g2
        float G1 = (p2 ? B1 : A1) + __shfl_xor_sync(0xffffffffu, t1, 2); // gate 2*g2+1

        // Stage 3 (xor 4): gather the other gate-half for the same row.
        float R0 = __shfl_xor_sync(0xffffffffu, G0, 4);
        float R1 = __shfl_xor_sync(0xffffffffu, G1, 4);
        float Gi = g2 ? R0 : G0;
        float Gf = g2 ? R1 : G1;
        float Gg = g2 ? G0 : R0;
        float Go = g2 ? G1 : R1;

        // ---- pointwise LSTM cell update for (row s, feature j) ----
        float gi = sigf(Gi);
        float gf = sigf(Gf);
        float gg = tanh_fast(Gg);
        float go = sigf(Go);
        c_st   = gf * c_st + gi * gg;
        h_last = go * tanh_fast(c_st);

        // ---- write next buffer: x_{t+1} and h_t ----
        float* vn = v_s + (buf ^ 1) * (RPB * VP);
        if (tid < RPB * Dn) vn[r_l * VP + d_l] = xv;
        if (valid && g2 == 0) vn[s * VP + Dn + j] = h_last;

        buf ^= 1;
        __syncthreads();   // the ONE barrier per step
    }

    if (valid && g2 == 0) g_hT[(row0 + s) * Hn + j] = h_last;
}

// ---- BN stats + folded FC weights: one block per feature ----
__global__ void bn_stats_kernel(
    const float* __restrict__ gamma,
    const float* __restrict__ beta,
    const float* __restrict__ fcw)
{
    __shared__ float sm[64], sm2[64];
    const int f   = blockIdx.x;   // 0..65
    const int tid = threadIdx.x;  // 64 threads

    float s = 0.0f, sq = 0.0f;
    for (int b = tid; b < Bsz; b += 64) {
        float v = g_hT[b * Hn + f];
        s += v; sq += v * v;
    }
    sm[tid] = s; sm2[tid] = sq;
    __syncthreads();
    for (int o = 32; o > 0; o >>= 1) {
        if (tid < o) { sm[tid] += sm[tid + o]; sm2[tid] += sm2[tid + o]; }
        __syncthreads();
    }
    if (tid == 0) {
        float mean = sm[0] * (1.0f / Bsz);
        float var  = sm2[0] * (1.0f / Bsz) - mean * mean;  // biased (jnp.var)
        float rs   = rsqrtf(var + 1e-5f);
        float wv   = gamma[f] * rs * fcw[f];
        g_wp[f] = wv;
        g_pc[f] = beta[f] * fcw[f] - mean * wv;
    }
}

// logits[b] = fc_b + sum_j pc[j] + sum_j hT[b][j]*wp[j]   (all L2-resident)
__global__ void fc_kernel(const float* __restrict__ fcb, float* __restrict__ out)
{
    const int b = blockIdx.x * blockDim.x + threadIdx.x;
    if (b >= Bsz) return;
    float acc = fcb[0];
    #pragma unroll
    for (int j = 0; j < Hn; ++j) acc += g_pc[j];
    #pragma unroll
    for (int j = 0; j < Hn; ++j) acc += g_hT[b * Hn + j] * g_wp[j];
    out[b] = acc;
}

extern "C" void kernel_launch(void* const* d_in, const int* in_sizes, int n_in,
                              void* d_out, int out_size)
{
    const float* x     = (const float*)d_in[0];
    const float* W_ih  = (const float*)d_in[1];
    const float* W_hh  = (const float*)d_in[2];
    const float* b_ih  = (const float*)d_in[3];
    const float* b_hh  = (const float*)d_in[4];
    const float* gamma = (const float*)d_in[5];
    const float* beta  = (const float*)d_in[6];
    const float* fcw   = (const float*)d_in[7];
    const float* fcb   = (const float*)d_in[8];

    lstm_kernel<<<NBLK, NTHR>>>(x, W_ih, W_hh, b_ih, b_hh);
    bn_stats_kernel<<<Hn, 64>>>(gamma, beta, fcw);
    fc_kernel<<<2, 256>>>(fcb, (float*)d_out);
}